// round 3
// baseline (speedup 1.0000x reference)
#include <cuda_runtime.h>
#include <cstdint>

#define Bsz  4096
#define Tst  128
#define NL   256
#define NOt  32
#define Vt   64
#define KB   32        // k per W1 stage
#define NST  8         // 256/KB stages
#define MT   32        // batch rows per CTA
#define SX   36        // xs row stride (k-major [NL][SX]); mult of 4 for LDS.128
#define SLG  36        // logits row stride

typedef unsigned long long ull;

__device__ __forceinline__ ull pk2(float lo, float hi) {
    ull r; asm("mov.b64 %0, {%1, %2};" : "=l"(r) : "f"(lo), "f"(hi)); return r;
}
__device__ __forceinline__ float2 upk2(ull v) {
    float2 r; asm("mov.b64 {%0, %1}, %2;" : "=f"(r.x), "=f"(r.y) : "l"(v)); return r;
}
__device__ __forceinline__ void fma2(ull &d, ull a, ull b) {
    asm("fma.rn.f32x2 %0, %1, %2, %0;" : "+l"(d) : "l"(a), "l"(b));
}

// smem layout (floats)
#define OF_XS   0
#define OF_WS   (OF_XS + NL * SX)           // 9216 : [2][KB][NL]
#define OF_W2   (OF_WS + 2 * KB * NL)       // 25600: [NL][32] k-major W2
#define OF_LG   (OF_W2 + NL * 32)           // 33792: [32][SLG]
#define OF_YB   (OF_LG + 32 * SLG)          // per-warp scatter buf [16][64]
#define OF_B2   (OF_YB + 16 * 64)           // [32]
#define OF_SQ   (OF_B2 + 32)                // [128] ints
#define SMEMF   (OF_SQ + 128)

__global__ void __launch_bounds__(512, 1) lalr_all(
    const float* __restrict__ latent0,
    const float* __restrict__ W1, const float* __restrict__ b1,
    const float* __restrict__ W2, const float* __restrict__ b2,
    const int*   __restrict__ state_seq, const int* __restrict__ out_idx,
    float* __restrict__ out)
{
    extern __shared__ float sm[];
    float* xs  = sm + OF_XS;
    float* ws  = sm + OF_WS;
    float* w2s = sm + OF_W2;
    float* lg  = sm + OF_LG;
    float* yb  = sm + OF_YB;
    float* b2s = sm + OF_B2;
    int*  sseq = (int*)(sm + OF_SQ);

    const int tid = threadIdx.x;
    const int w = tid >> 5, l = tid & 31;
    const int rowbase = blockIdx.x * MT;

    // ---- GEMM1 lane mapping: warp w owns cols [w*16, +16); lane: 8 rows x 2 cols
    const int rg = (l >> 3) * 8;            // 0,8,16,24
    const int c0 = w * 16 + (l & 7) * 2;    // 2 cols
    // ---- GEMM2 mapping: 32 rows x 2 k-halves x 8 out-quads
    const int r2 = tid >> 4;
    const int kh = (tid >> 3) & 1;
    const int oq = tid & 7;
    // ---- W1 stage-fill mapping: n = tid&255, k-half = tid>>8
    const int sfn = tid & 255;
    const int sfk = (tid >> 8) * 16;

    // ---- init: state_seq to smem; latent0 -> xs (k-major transpose)
    if (tid < Tst) sseq[tid] = state_seq[tid];
    {
        int r = tid >> 4, kq = (tid & 15) * 16;
        const float* src = latent0 + (size_t)(rowbase + r) * NL + kq;
        #pragma unroll
        for (int j = 0; j < 4; j++) {
            float4 v = *(const float4*)(src + j * 4);
            int k = kq + j * 4;
            xs[(k + 0) * SX + r] = v.x;
            xs[(k + 1) * SX + r] = v.y;
            xs[(k + 2) * SX + r] = v.z;
            xs[(k + 3) * SX + r] = v.w;
        }
    }
    __syncthreads();

    for (int t = 0; t < Tst; t++) {
        const int s = sseq[t];
        const float* W1s = W1 + (size_t)s * NL * NL;
        const float* W2s = W2 + (size_t)s * NOt * NL;

        // ---- issue deep loads: W1 stage 0, W2, biases, out_idx ----
        const float* w1src = W1s + (size_t)sfn * NL + sfk;
        float4 p0 = *(const float4*)(w1src + 0);
        float4 p1 = *(const float4*)(w1src + 4);
        float4 p2 = *(const float4*)(w1src + 8);
        float4 p3 = *(const float4*)(w1src + 12);

        const int o2 = tid & 31, kq2 = (tid >> 5) * 16;
        const float* w2src = W2s + (size_t)o2 * NL + kq2;
        float4 q0 = *(const float4*)(w2src + 0);
        float4 q1 = *(const float4*)(w2src + 4);
        float4 q2 = *(const float4*)(w2src + 8);
        float4 q3 = *(const float4*)(w2src + 12);

        float2 b1v = *(const float2*)(b1 + s * NL + c0);
        int idxv = out_idx[s * NOt + l];
        if (tid < NOt) b2s[tid] = b2[s * NOt + tid];

        // ---- STS W1 stage 0 (buf 0) ----
        {
            float* d = ws;
            d[(sfk + 0) * NL + sfn] = p0.x; d[(sfk + 1) * NL + sfn] = p0.y;
            d[(sfk + 2) * NL + sfn] = p0.z; d[(sfk + 3) * NL + sfn] = p0.w;
            d[(sfk + 4) * NL + sfn] = p1.x; d[(sfk + 5) * NL + sfn] = p1.y;
            d[(sfk + 6) * NL + sfn] = p1.z; d[(sfk + 7) * NL + sfn] = p1.w;
            d[(sfk + 8) * NL + sfn] = p2.x; d[(sfk + 9) * NL + sfn] = p2.y;
            d[(sfk + 10) * NL + sfn] = p2.z; d[(sfk + 11) * NL + sfn] = p2.w;
            d[(sfk + 12) * NL + sfn] = p3.x; d[(sfk + 13) * NL + sfn] = p3.y;
            d[(sfk + 14) * NL + sfn] = p3.z; d[(sfk + 15) * NL + sfn] = p3.w;
        }
        // ---- LDG W1 stage 1 ----
        p0 = *(const float4*)(w1src + KB + 0);
        p1 = *(const float4*)(w1src + KB + 4);
        p2 = *(const float4*)(w1src + KB + 8);
        p3 = *(const float4*)(w1src + KB + 12);
        // ---- STS W2 (k-major) ----
        {
            #pragma unroll
            for (int i = 0; i < 4; i++) {
                w2s[(kq2 + 0 * 4 + i) * 32 + o2] = ((const float*)&q0)[i];
                w2s[(kq2 + 1 * 4 + i) * 32 + o2] = ((const float*)&q1)[i];
                w2s[(kq2 + 2 * 4 + i) * 32 + o2] = ((const float*)&q2)[i];
                w2s[(kq2 + 3 * 4 + i) * 32 + o2] = ((const float*)&q3)[i];
            }
        }
        __syncthreads();

        // ---- GEMM1: acc[4 row-pairs][2 cols], pipelined stages ----
        ull acc[4][2];
        #pragma unroll
        for (int p = 0; p < 4; p++) { acc[p][0] = 0ull; acc[p][1] = 0ull; }

        for (int kt = 0; kt < NST; kt++) {
            if (kt + 1 < NST) {
                // publish stage kt+1 (regs loaded during kt-1 / prologue)
                float* d = ws + ((kt + 1) & 1) * KB * NL;
                d[(sfk + 0) * NL + sfn] = p0.x; d[(sfk + 1) * NL + sfn] = p0.y;
                d[(sfk + 2) * NL + sfn] = p0.z; d[(sfk + 3) * NL + sfn] = p0.w;
                d[(sfk + 4) * NL + sfn] = p1.x; d[(sfk + 5) * NL + sfn] = p1.y;
                d[(sfk + 6) * NL + sfn] = p1.z; d[(sfk + 7) * NL + sfn] = p1.w;
                d[(sfk + 8) * NL + sfn] = p2.x; d[(sfk + 9) * NL + sfn] = p2.y;
                d[(sfk + 10) * NL + sfn] = p2.z; d[(sfk + 11) * NL + sfn] = p2.w;
                d[(sfk + 12) * NL + sfn] = p3.x; d[(sfk + 13) * NL + sfn] = p3.y;
                d[(sfk + 14) * NL + sfn] = p3.z; d[(sfk + 15) * NL + sfn] = p3.w;
                if (kt + 2 < NST) {
                    const float* src = w1src + (kt + 2) * KB;
                    p0 = *(const float4*)(src + 0);
                    p1 = *(const float4*)(src + 4);
                    p2 = *(const float4*)(src + 8);
                    p3 = *(const float4*)(src + 12);
                }
            }
            const float* wp = ws + (kt & 1) * KB * NL + c0;
            const float* xp = xs + (kt * KB) * SX + rg;
            #pragma unroll 8
            for (int kk = 0; kk < KB; kk++) {
                ulonglong2 X0 = *(const ulonglong2*)(xp);       // rows rg..rg+3
                ulonglong2 X1 = *(const ulonglong2*)(xp + 4);   // rows rg+4..rg+7
                float2 wv = *(const float2*)(wp);
                ull wa = pk2(wv.x, wv.x);
                ull wb = pk2(wv.y, wv.y);
                fma2(acc[0][0], X0.x, wa); fma2(acc[1][0], X0.y, wa);
                fma2(acc[2][0], X1.x, wa); fma2(acc[3][0], X1.y, wa);
                fma2(acc[0][1], X0.x, wb); fma2(acc[1][1], X0.y, wb);
                fma2(acc[2][1], X1.x, wb); fma2(acc[3][1], X1.y, wb);
                xp += SX; wp += NL;
            }
            __syncthreads();
        }

        // ---- epilogue: tanh(acc + b1), write x_new k-major into xs ----
        {
            #pragma unroll
            for (int c = 0; c < 2; c++) {
                float bb = (c == 0) ? b1v.x : b1v.y;
                float4 lo, hi;
                float2 u0 = upk2(acc[0][c]);
                float2 u1 = upk2(acc[1][c]);
                float2 u2 = upk2(acc[2][c]);
                float2 u3 = upk2(acc[3][c]);
                lo.x = tanhf(u0.x + bb); lo.y = tanhf(u0.y + bb);
                lo.z = tanhf(u1.x + bb); lo.w = tanhf(u1.y + bb);
                hi.x = tanhf(u2.x + bb); hi.y = tanhf(u2.y + bb);
                hi.z = tanhf(u3.x + bb); hi.w = tanhf(u3.y + bb);
                *(float4*)(xs + (c0 + c) * SX + rg)     = lo;
                *(float4*)(xs + (c0 + c) * SX + rg + 4) = hi;
            }
        }
        __syncthreads();

        // ---- GEMM2: logits[r][o] = x_new[r] . W2[o] + b2 (split-k over 2 halves) ----
        {
            ull a0 = 0ull, a1 = 0ull;
            const float* xq = xs + (kh * 128) * SX + r2;
            const float* wq = w2s + (kh * 128) * 32 + oq * 4;
            #pragma unroll 8
            for (int i = 0; i < 128; i++) {
                float xv = *xq;
                ull xx = pk2(xv, xv);
                ulonglong2 wv = *(const ulonglong2*)(wq);
                fma2(a0, xx, wv.x);
                fma2(a1, xx, wv.y);
                xq += SX; wq += 32;
            }
            ull m0 = __shfl_xor_sync(0xffffffffu, a0, 8);
            ull m1 = __shfl_xor_sync(0xffffffffu, a1, 8);
            if (kh == 0) {
                float2 A0 = upk2(a0), A1 = upk2(a1);
                float2 P0 = upk2(m0), P1 = upk2(m1);
                float4 r4;
                r4.x = A0.x + P0.x + b2s[oq * 4 + 0];
                r4.y = A0.y + P0.y + b2s[oq * 4 + 1];
                r4.z = A1.x + P1.x + b2s[oq * 4 + 2];
                r4.w = A1.y + P1.y + b2s[oq * 4 + 3];
                *(float4*)(lg + r2 * SLG + oq * 4) = r4;
            }
        }
        __syncthreads();

        // ---- softmax + last-write-wins scatter + store: warp handles rows 2w, 2w+1 ----
        {
            float* y = yb + w * 64;
            unsigned mset = __match_any_sync(0xffffffffu, idxv);
            bool leader = (31 - __clz(mset)) == l;
            #pragma unroll
            for (int rr = 0; rr < 2; rr++) {
                int row = w * 2 + rr;
                float v = lg[row * SLG + l];
                float m = v;
                #pragma unroll
                for (int off = 16; off > 0; off >>= 1)
                    m = fmaxf(m, __shfl_xor_sync(0xffffffffu, m, off));
                float e = __expf(v - m);
                float ssum = e;
                #pragma unroll
                for (int off = 16; off > 0; off >>= 1)
                    ssum += __shfl_xor_sync(0xffffffffu, ssum, off);
                float p = e / ssum;
                y[l] = 0.f; y[l + 32] = 0.f;
                __syncwarp();
                if (leader) y[idxv] = p;
                __syncwarp();
                float* op = out + (size_t)(rowbase + row) * (Tst * Vt) + (size_t)t * Vt;
                op[l]      = y[l];
                op[l + 32] = y[l + 32];
                __syncwarp();
            }
        }
        __syncthreads();
    }
}

extern "C" void kernel_launch(void* const* d_in, const int* in_sizes, int n_in,
                              void* d_out, int out_size)
{
    const float* latent0   = (const float*)d_in[0];
    const float* W1        = (const float*)d_in[1];
    const float* b1        = (const float*)d_in[2];
    const float* W2        = (const float*)d_in[3];
    const float* b2        = (const float*)d_in[4];
    const int*   state_seq = (const int*)  d_in[5];
    const int*   out_idx   = (const int*)  d_in[6];
    float* out = (float*)d_out;

    const int smem_bytes = SMEMF * (int)sizeof(float);   // ~144.5 KB
    cudaFuncSetAttribute(lalr_all, cudaFuncAttributeMaxDynamicSharedMemorySize, smem_bytes);

    lalr_all<<<Bsz / MT, 512, smem_bytes>>>(
        latent0, W1, b1, W2, b2, state_seq, out_idx, out);
}

// round 4
// speedup vs baseline: 1.2607x; 1.2607x over previous
#include <cuda_runtime.h>
#include <cstdint>

#define Bsz  4096
#define Tst  128
#define NL   256
#define NOt  32
#define Vt   64
#define KB   32         // k per W1 stage
#define NST  8          // 256/KB stages
#define MT   32         // batch rows per CTA
#define SX   36         // xs row stride
#define SLG  36
#define WCOL 16         // W1 cols owned per warp

typedef unsigned long long ull;

__device__ __forceinline__ ull pk2(float lo, float hi) {
    ull r; asm("mov.b64 %0, {%1, %2};" : "=l"(r) : "f"(lo), "f"(hi)); return r;
}
__device__ __forceinline__ float2 upk2(ull v) {
    float2 r; asm("mov.b64 {%0, %1}, %2;" : "=f"(r.x), "=f"(r.y) : "l"(v)); return r;
}
__device__ __forceinline__ void fma2(ull &d, ull a, ull b) {
    asm("fma.rn.f32x2 %0, %1, %2, %0;" : "+l"(d) : "l"(a), "l"(b));
}

// smem float offsets
#define OF_XS0  0
#define OF_XS1  (OF_XS0 + NL * SX)           //  9216
#define OF_WS   (OF_XS1 + NL * SX)           // 18432 : 16 warps x [2][KB][16]
#define OF_W2   (OF_WS + 16 * 2 * KB * WCOL) // 34816 : [NL][32] k-major
#define OF_LG   (OF_W2 + NL * 32)            // 43008 : [32][SLG]
#define OF_YB   (OF_LG + 32 * SLG)           // 44160 : [16][64]
#define OF_B2   (OF_YB + 16 * 64)            // 45184
#define OF_SQ   (OF_B2 + 32)                 // 45216
#define SMEMF   (OF_SQ + 128)                // 45344 floats = 181376 B

__global__ void __launch_bounds__(512, 1) lalr_all(
    const float* __restrict__ latent0,
    const float* __restrict__ W1, const float* __restrict__ b1,
    const float* __restrict__ W2, const float* __restrict__ b2,
    const int*   __restrict__ state_seq, const int* __restrict__ out_idx,
    float* __restrict__ out)
{
    extern __shared__ float sm[];
    float* w2s = sm + OF_W2;
    float* lg  = sm + OF_LG;
    float* yb  = sm + OF_YB;
    float* b2s = sm + OF_B2;
    int*  sseq = (int*)(sm + OF_SQ);

    const int tid = threadIdx.x;
    const int w = tid >> 5, l = tid & 31;
    const int rowbase = blockIdx.x * MT;

    // GEMM1 mapping: warp owns cols [16w,16w+16); lane: 8 rows x 2 cols
    const int rg   = (l >> 3) * 8;
    const int coff = (l & 7) * 2;
    const int c0   = w * WCOL + coff;
    float* wsw = sm + OF_WS + w * (2 * KB * WCOL);   // warp-private W1 stage

    // W1 stage-fill mapping (warp-local): lane -> col r1f in [0,16), k-half
    const int r1f = l >> 1;
    const int khf = (l & 1) * 16;

    // GEMM2 mapping
    const int r2  = tid >> 4;
    const int kh2 = (tid >> 3) & 1;
    const int oq  = tid & 7;

    // W2 fill mapping
    const int o2  = tid & 31;
    const int kq2 = (tid >> 5) * 16;

    // ---- init ----
    if (tid < Tst) sseq[tid] = state_seq[tid];
    {
        float* xs0 = sm + OF_XS0;
        int r = tid >> 4, kq = (tid & 15) * 16;
        const float* src = latent0 + (size_t)(rowbase + r) * NL + kq;
        #pragma unroll
        for (int j = 0; j < 4; j++) {
            float4 v = *(const float4*)(src + j * 4);
            int k = kq + j * 4;
            xs0[(k + 0) * SX + r] = v.x;
            xs0[(k + 1) * SX + r] = v.y;
            xs0[(k + 2) * SX + r] = v.z;
            xs0[(k + 3) * SX + r] = v.w;
        }
    }
    __syncthreads();

    // ---- prologue loads for t=0 ----
    int s = sseq[0];
    const float* w1src = W1 + (size_t)s * NL * NL + (size_t)(w * WCOL + r1f) * NL + khf;
    float4 p0 = *(const float4*)(w1src + 0);
    float4 p1 = *(const float4*)(w1src + 4);
    float4 p2 = *(const float4*)(w1src + 8);
    float4 p3 = *(const float4*)(w1src + 12);
    const float* w2src = W2 + (size_t)s * NOt * NL + (size_t)o2 * NL + kq2;
    float4 q0 = *(const float4*)(w2src + 0);
    float4 q1 = *(const float4*)(w2src + 4);
    float4 q2 = *(const float4*)(w2src + 8);
    float4 q3 = *(const float4*)(w2src + 12);
    float b2r = (tid < NOt) ? b2[s * NOt + tid] : 0.f;

    for (int t = 0; t < Tst; t++) {
        const float* xs_cur = sm + ((t & 1) ? OF_XS1 : OF_XS0);
        float*       xs_nxt = sm + ((t & 1) ? OF_XS0 : OF_XS1);

        float2 b1v = *(const float2*)(b1 + s * NL + c0);
        int idxv = out_idx[s * NOt + l];

        // publish W1 stage 0 (warp-private) and W2 (block-shared)
        {
            float* d = wsw;
            d[(khf + 0) * WCOL + r1f] = p0.x;  d[(khf + 1) * WCOL + r1f] = p0.y;
            d[(khf + 2) * WCOL + r1f] = p0.z;  d[(khf + 3) * WCOL + r1f] = p0.w;
            d[(khf + 4) * WCOL + r1f] = p1.x;  d[(khf + 5) * WCOL + r1f] = p1.y;
            d[(khf + 6) * WCOL + r1f] = p1.z;  d[(khf + 7) * WCOL + r1f] = p1.w;
            d[(khf + 8) * WCOL + r1f] = p2.x;  d[(khf + 9) * WCOL + r1f] = p2.y;
            d[(khf + 10) * WCOL + r1f] = p2.z; d[(khf + 11) * WCOL + r1f] = p2.w;
            d[(khf + 12) * WCOL + r1f] = p3.x; d[(khf + 13) * WCOL + r1f] = p3.y;
            d[(khf + 14) * WCOL + r1f] = p3.z; d[(khf + 15) * WCOL + r1f] = p3.w;
        }
        // prefetch W1 stage 1
        p0 = *(const float4*)(w1src + KB + 0);
        p1 = *(const float4*)(w1src + KB + 4);
        p2 = *(const float4*)(w1src + KB + 8);
        p3 = *(const float4*)(w1src + KB + 12);
        // W2 -> smem k-major (loaded last tail / prologue, latency long covered)
        #pragma unroll
        for (int i = 0; i < 4; i++) {
            w2s[(kq2 + 0 + i) * 32 + o2]  = ((const float*)&q0)[i];
            w2s[(kq2 + 4 + i) * 32 + o2]  = ((const float*)&q1)[i];
            w2s[(kq2 + 8 + i) * 32 + o2]  = ((const float*)&q2)[i];
            w2s[(kq2 + 12 + i) * 32 + o2] = ((const float*)&q3)[i];
        }
        if (tid < NOt) b2s[tid] = b2r;
        __syncwarp();

        // ---- GEMM1 (no block barriers) ----
        ull acc[4][2];
        #pragma unroll
        for (int p = 0; p < 4; p++) { acc[p][0] = 0ull; acc[p][1] = 0ull; }

        for (int kt = 0; kt < NST; kt++) {
            const float* wp = wsw + (kt & 1) * KB * WCOL + coff;
            const float* xp = xs_cur + (kt * KB) * SX + rg;
            #pragma unroll 8
            for (int kk = 0; kk < KB; kk++) {
                ulonglong2 X0 = *(const ulonglong2*)(xp);
                ulonglong2 X1 = *(const ulonglong2*)(xp + 4);
                float2 wv = *(const float2*)(wp);
                ull wa = pk2(wv.x, wv.x);
                ull wb = pk2(wv.y, wv.y);
                fma2(acc[0][0], X0.x, wa); fma2(acc[1][0], X0.y, wa);
                fma2(acc[2][0], X1.x, wa); fma2(acc[3][0], X1.y, wa);
                fma2(acc[0][1], X0.x, wb); fma2(acc[1][1], X0.y, wb);
                fma2(acc[2][1], X1.x, wb); fma2(acc[3][1], X1.y, wb);
                xp += SX; wp += WCOL;
            }
            if (kt + 1 < NST) {
                float* d = wsw + ((kt + 1) & 1) * KB * WCOL;
                d[(khf + 0) * WCOL + r1f] = p0.x;  d[(khf + 1) * WCOL + r1f] = p0.y;
                d[(khf + 2) * WCOL + r1f] = p0.z;  d[(khf + 3) * WCOL + r1f] = p0.w;
                d[(khf + 4) * WCOL + r1f] = p1.x;  d[(khf + 5) * WCOL + r1f] = p1.y;
                d[(khf + 6) * WCOL + r1f] = p1.z;  d[(khf + 7) * WCOL + r1f] = p1.w;
                d[(khf + 8) * WCOL + r1f] = p2.x;  d[(khf + 9) * WCOL + r1f] = p2.y;
                d[(khf + 10) * WCOL + r1f] = p2.z; d[(khf + 11) * WCOL + r1f] = p2.w;
                d[(khf + 12) * WCOL + r1f] = p3.x; d[(khf + 13) * WCOL + r1f] = p3.y;
                d[(khf + 14) * WCOL + r1f] = p3.z; d[(khf + 15) * WCOL + r1f] = p3.w;
                if (kt + 2 < NST) {
                    const float* src = w1src + (kt + 2) * KB;
                    p0 = *(const float4*)(src + 0);
                    p1 = *(const float4*)(src + 4);
                    p2 = *(const float4*)(src + 8);
                    p3 = *(const float4*)(src + 12);
                }
                __syncwarp();
            }
        }

        // ---- tail prefetch for step t+1 (covered by epilogue+GEMM2+softmax) ----
        s = sseq[(t + 1) & (Tst - 1)];
        w1src = W1 + (size_t)s * NL * NL + (size_t)(w * WCOL + r1f) * NL + khf;
        p0 = *(const float4*)(w1src + 0);
        p1 = *(const float4*)(w1src + 4);
        p2 = *(const float4*)(w1src + 8);
        p3 = *(const float4*)(w1src + 12);
        w2src = W2 + (size_t)s * NOt * NL + (size_t)o2 * NL + kq2;
        q0 = *(const float4*)(w2src + 0);
        q1 = *(const float4*)(w2src + 4);
        q2 = *(const float4*)(w2src + 8);
        q3 = *(const float4*)(w2src + 12);
        b2r = (tid < NOt) ? b2[s * NOt + tid] : 0.f;

        // ---- epilogue: tanh -> xs_nxt (k-major) ----
        #pragma unroll
        for (int c = 0; c < 2; c++) {
            float bb = (c == 0) ? b1v.x : b1v.y;
            float4 lo, hi;
            float2 u0 = upk2(acc[0][c]);
            float2 u1 = upk2(acc[1][c]);
            float2 u2 = upk2(acc[2][c]);
            float2 u3 = upk2(acc[3][c]);
            lo.x = tanhf(u0.x + bb); lo.y = tanhf(u0.y + bb);
            lo.z = tanhf(u1.x + bb); lo.w = tanhf(u1.y + bb);
            hi.x = tanhf(u2.x + bb); hi.y = tanhf(u2.y + bb);
            hi.z = tanhf(u3.x + bb); hi.w = tanhf(u3.y + bb);
            *(float4*)(xs_nxt + (c0 + c) * SX + rg)     = lo;
            *(float4*)(xs_nxt + (c0 + c) * SX + rg + 4) = hi;
        }
        __syncthreads();

        // ---- GEMM2: logits = x_new @ W2^T + b2 (split-k 2) ----
        {
            ull a0 = 0ull, a1 = 0ull;
            const float* xq = xs_nxt + (kh2 * 128) * SX + r2;
            const float* wq = w2s + (kh2 * 128) * 32 + oq * 4;
            #pragma unroll 8
            for (int i = 0; i < 128; i++) {
                float xv = *xq;
                ull xx = pk2(xv, xv);
                ulonglong2 wv = *(const ulonglong2*)(wq);
                fma2(a0, xx, wv.x);
                fma2(a1, xx, wv.y);
                xq += SX; wq += 32;
            }
            ull m0 = __shfl_xor_sync(0xffffffffu, a0, 8);
            ull m1 = __shfl_xor_sync(0xffffffffu, a1, 8);
            if (kh2 == 0) {
                float2 A0 = upk2(a0), A1 = upk2(a1);
                float2 P0 = upk2(m0), P1 = upk2(m1);
                float4 r4;
                r4.x = A0.x + P0.x + b2s[oq * 4 + 0];
                r4.y = A0.y + P0.y + b2s[oq * 4 + 1];
                r4.z = A1.x + P1.x + b2s[oq * 4 + 2];
                r4.w = A1.y + P1.y + b2s[oq * 4 + 3];
                *(float4*)(lg + r2 * SLG + oq * 4) = r4;
            }
        }
        __syncthreads();

        // ---- softmax + last-write-wins scatter + out ----
        {
            float* y = yb + w * 64;
            unsigned mset = __match_any_sync(0xffffffffu, idxv);
            bool leader = (31 - __clz(mset)) == l;
            #pragma unroll
            for (int rr = 0; rr < 2; rr++) {
                int row = w * 2 + rr;
                float v = lg[row * SLG + l];
                float m = v;
                #pragma unroll
                for (int off = 16; off > 0; off >>= 1)
                    m = fmaxf(m, __shfl_xor_sync(0xffffffffu, m, off));
                float e = __expf(v - m);
                float ssum = e;
                #pragma unroll
                for (int off = 16; off > 0; off >>= 1)
                    ssum += __shfl_xor_sync(0xffffffffu, ssum, off);
                float p = e / ssum;
                y[l] = 0.f; y[l + 32] = 0.f;
                __syncwarp();
                if (leader) y[idxv] = p;
                __syncwarp();
                float* op = out + (size_t)(rowbase + row) * (Tst * Vt) + (size_t)t * Vt;
                *(float2*)(op + 2 * l) = *(const float2*)(y + 2 * l);
                __syncwarp();
            }
        }
        // no barrier needed here: next-step writes to lg/w2s/xs are gated by
        // this step's two barriers (see ordering argument in commit msg)
    }
}

extern "C" void kernel_launch(void* const* d_in, const int* in_sizes, int n_in,
                              void* d_out, int out_size)
{
    const float* latent0   = (const float*)d_in[0];
    const float* W1        = (const float*)d_in[1];
    const float* b1        = (const float*)d_in[2];
    const float* W2        = (const float*)d_in[3];
    const float* b2        = (const float*)d_in[4];
    const int*   state_seq = (const int*)  d_in[5];
    const int*   out_idx   = (const int*)  d_in[6];
    float* out = (float*)d_out;

    const int smem_bytes = SMEMF * (int)sizeof(float);   // ~177 KB
    cudaFuncSetAttribute(lalr_all, cudaFuncAttributeMaxDynamicSharedMemorySize, smem_bytes);

    lalr_all<<<Bsz / MT, 512, smem_bytes>>>(
        latent0, W1, b1, W2, b2, state_seq, out_idx, out);
}